// round 1
// baseline (speedup 1.0000x reference)
#include <cuda_runtime.h>
#include <math_constants.h>

#define D_MODEL 768
#define NHEAD   12
#define DK      64
#define MAXM    8192   // B*S = 2*4096

// ---- scratch (no cudaMalloc allowed) ----
__device__ float g_q [MAXM * D_MODEL];
__device__ float g_k [MAXM * D_MODEL];
__device__ float g_v [MAXM * D_MODEL];
__device__ float g_ao[MAXM * D_MODEL];

// ============================================================================
// NT GEMM: C[m][n] = bias[n] + sum_k A[m][k] * W[n][k]
// A: MxK row-major, W: NxK row-major, C: MxN row-major.
// 64x64 tile, BK=16, 256 threads, 4x4 per thread.
// ============================================================================
__global__ __launch_bounds__(256) void gemm_nt_bias(
    const float* __restrict__ A, const float* __restrict__ W,
    const float* __restrict__ bias, float* __restrict__ C,
    int M, int N, int K)
{
    __shared__ float As[16][68];   // [k][m]
    __shared__ float Bs[16][68];   // [k][n]
    const int tid = threadIdx.x;
    const int tx = tid & 15, ty = tid >> 4;
    const int bm = blockIdx.y * 64, bn = blockIdx.x * 64;
    const int lrow = tid >> 2;          // 0..63
    const int lcol = (tid & 3) << 2;    // 0,4,8,12
    const float* Ap = A + (size_t)(bm + lrow) * K + lcol;
    const float* Wp = W + (size_t)(bn + lrow) * K + lcol;

    float acc[4][4] = {};

    for (int k0 = 0; k0 < K; k0 += 16) {
        float4 a = *(const float4*)(Ap + k0);
        float4 w = *(const float4*)(Wp + k0);
        As[lcol+0][lrow]=a.x; As[lcol+1][lrow]=a.y; As[lcol+2][lrow]=a.z; As[lcol+3][lrow]=a.w;
        Bs[lcol+0][lrow]=w.x; Bs[lcol+1][lrow]=w.y; Bs[lcol+2][lrow]=w.z; Bs[lcol+3][lrow]=w.w;
        __syncthreads();
#pragma unroll
        for (int kk = 0; kk < 16; kk++) {
            float4 av = *(const float4*)&As[kk][ty<<2];
            float4 wv = *(const float4*)&Bs[kk][tx<<2];
            float a0[4] = {av.x, av.y, av.z, av.w};
            float w0[4] = {wv.x, wv.y, wv.z, wv.w};
#pragma unroll
            for (int i = 0; i < 4; i++)
#pragma unroll
                for (int j = 0; j < 4; j++)
                    acc[i][j] = fmaf(a0[i], w0[j], acc[i][j]);
        }
        __syncthreads();
    }

    float4 bv = *(const float4*)(bias + bn + (tx<<2));
    float bj[4] = {bv.x, bv.y, bv.z, bv.w};
#pragma unroll
    for (int i = 0; i < 4; i++) {
        float4 o;
        o.x = acc[i][0] + bj[0];
        o.y = acc[i][1] + bj[1];
        o.z = acc[i][2] + bj[2];
        o.w = acc[i][3] + bj[3];
        *(float4*)(C + (size_t)(bm + (ty<<2) + i) * N + bn + (tx<<2)) = o;
    }
}

// ============================================================================
// Flash attention, fp32. One CTA = 64 query rows of one (b,h).
// q,k,v,o layout: (B, S, H*DK). scale folded into Q load.
// ============================================================================
#define SMEM_FLASH (4 * 64 * 68 * 4)

__global__ __launch_bounds__(256) void flash_attn(
    const float* __restrict__ Qp, const float* __restrict__ Kp,
    const float* __restrict__ Vp, float* __restrict__ Op, int S)
{
    extern __shared__ float smf[];
    float (*Qts)[68] = (float (*)[68])(smf);            // [d][m] (transposed)
    float (*Kts)[68] = (float (*)[68])(smf + 1*64*68);  // [d][n] (transposed)
    float (*Vs )[68] = (float (*)[68])(smf + 2*64*68);  // [key][d]
    float (*Ps )[68] = (float (*)[68])(smf + 3*64*68);  // [q][key]

    const int tid = threadIdx.x;
    const int tx = tid & 15, ty = tid >> 4;
    const int bh = blockIdx.y;
    const int b = bh / NHEAD, h = bh % NHEAD;
    const int q0 = blockIdx.x * 64;
    const size_t base = ((size_t)b * S) * D_MODEL + (size_t)h * DK;
    const int lrow = tid >> 2;          // 0..63
    const int lcol = (tid & 3) << 2;    // 0,4,8,12

    // load Q tile transposed, pre-scaled by 1/sqrt(dk)=0.125
#pragma unroll
    for (int c = 0; c < 64; c += 16) {
        float4 qv = *(const float4*)(Qp + base + (size_t)(q0 + lrow) * D_MODEL + lcol + c);
        Qts[lcol+c+0][lrow] = qv.x * 0.125f;
        Qts[lcol+c+1][lrow] = qv.y * 0.125f;
        Qts[lcol+c+2][lrow] = qv.z * 0.125f;
        Qts[lcol+c+3][lrow] = qv.w * 0.125f;
    }

    float m_i[4], l_i[4], acc[4][4];
#pragma unroll
    for (int i = 0; i < 4; i++) {
        m_i[i] = -CUDART_INF_F; l_i[i] = 0.f;
#pragma unroll
        for (int j = 0; j < 4; j++) acc[i][j] = 0.f;
    }

    for (int kv0 = 0; kv0 < S; kv0 += 64) {
        // load K (transposed) and V (natural) tiles
#pragma unroll
        for (int c = 0; c < 64; c += 16) {
            float4 kvv = *(const float4*)(Kp + base + (size_t)(kv0 + lrow) * D_MODEL + lcol + c);
            Kts[lcol+c+0][lrow] = kvv.x;
            Kts[lcol+c+1][lrow] = kvv.y;
            Kts[lcol+c+2][lrow] = kvv.z;
            Kts[lcol+c+3][lrow] = kvv.w;
            float4 vv = *(const float4*)(Vp + base + (size_t)(kv0 + lrow) * D_MODEL + lcol + c);
            *(float4*)&Vs[lrow][lcol + c] = vv;
        }
        __syncthreads();

        // S = (Q*scale) @ K^T  (64x64, inner dim 64)
        float s[4][4] = {};
#pragma unroll
        for (int d = 0; d < 64; d++) {
            float4 qf = *(const float4*)&Qts[d][ty<<2];
            float4 kf = *(const float4*)&Kts[d][tx<<2];
            float qa[4] = {qf.x, qf.y, qf.z, qf.w};
            float ka[4] = {kf.x, kf.y, kf.z, kf.w};
#pragma unroll
            for (int i = 0; i < 4; i++)
#pragma unroll
                for (int j = 0; j < 4; j++)
                    s[i][j] = fmaf(qa[i], ka[j], s[i][j]);
        }

        // online softmax update (rows shared by the 16 tx lanes -> shfl reduce)
#pragma unroll
        for (int i = 0; i < 4; i++) {
            float mx = fmaxf(fmaxf(s[i][0], s[i][1]), fmaxf(s[i][2], s[i][3]));
#pragma unroll
            for (int off = 8; off >= 1; off >>= 1)
                mx = fmaxf(mx, __shfl_xor_sync(0xffffffffu, mx, off));
            float mnew = fmaxf(m_i[i], mx);
            float alpha = __expf(m_i[i] - mnew);
            m_i[i] = mnew;
            float rs = 0.f;
#pragma unroll
            for (int j = 0; j < 4; j++) {
                float p = __expf(s[i][j] - mnew);
                s[i][j] = p;
                rs += p;
            }
#pragma unroll
            for (int off = 8; off >= 1; off >>= 1)
                rs += __shfl_xor_sync(0xffffffffu, rs, off);
            l_i[i] = l_i[i] * alpha + rs;
#pragma unroll
            for (int j = 0; j < 4; j++) acc[i][j] *= alpha;
        }

        // stage P to smem for P @ V
#pragma unroll
        for (int i = 0; i < 4; i++)
            *(float4*)&Ps[(ty<<2)+i][tx<<2] = make_float4(s[i][0], s[i][1], s[i][2], s[i][3]);
        __syncthreads();

        // O += P @ V  (inner dim = 64 keys)
#pragma unroll
        for (int kk = 0; kk < 64; kk++) {
            float p0 = Ps[(ty<<2)+0][kk];
            float p1 = Ps[(ty<<2)+1][kk];
            float p2 = Ps[(ty<<2)+2][kk];
            float p3 = Ps[(ty<<2)+3][kk];
            float4 vf = *(const float4*)&Vs[kk][tx<<2];
            float va[4] = {vf.x, vf.y, vf.z, vf.w};
#pragma unroll
            for (int j = 0; j < 4; j++) {
                acc[0][j] = fmaf(p0, va[j], acc[0][j]);
                acc[1][j] = fmaf(p1, va[j], acc[1][j]);
                acc[2][j] = fmaf(p2, va[j], acc[2][j]);
                acc[3][j] = fmaf(p3, va[j], acc[3][j]);
            }
        }
        __syncthreads();   // Vs/Kts reuse next iter
    }

    // epilogue: normalize and write in (B,S,H*DK) layout (head-merge for free)
#pragma unroll
    for (int i = 0; i < 4; i++) {
        float inv = 1.f / l_i[i];
        float4 o = make_float4(acc[i][0]*inv, acc[i][1]*inv, acc[i][2]*inv, acc[i][3]*inv);
        *(float4*)(Op + base + (size_t)(q0 + (ty<<2) + i) * D_MODEL + (tx<<2)) = o;
    }
}

// ============================================================================
extern "C" void kernel_launch(void* const* d_in, const int* in_sizes, int n_in,
                              void* d_out, int out_size)
{
    const float* Q  = (const float*)d_in[0];
    const float* K  = (const float*)d_in[1];
    const float* V  = (const float*)d_in[2];
    const float* Wq = (const float*)d_in[3];
    const float* bq = (const float*)d_in[4];
    const float* Wk = (const float*)d_in[5];
    const float* bk = (const float*)d_in[6];
    const float* Wv = (const float*)d_in[7];
    const float* bv = (const float*)d_in[8];
    const float* Wo = (const float*)d_in[9];
    const float* bo = (const float*)d_in[10];
    float* out = (float*)d_out;

    const int M = in_sizes[0] / D_MODEL;   // B*S
    const int S = 4096;
    const int B = M / S;

    float *gq, *gk, *gv, *go;
    cudaGetSymbolAddress((void**)&gq, g_q);
    cudaGetSymbolAddress((void**)&gk, g_k);
    cudaGetSymbolAddress((void**)&gv, g_v);
    cudaGetSymbolAddress((void**)&go, g_ao);

    cudaFuncSetAttribute(flash_attn, cudaFuncAttributeMaxDynamicSharedMemorySize, SMEM_FLASH);

    dim3 tb(256);
    dim3 gg(D_MODEL / 64, M / 64);
    gemm_nt_bias<<<gg, tb>>>(Q, Wq, bq, gq, M, D_MODEL, D_MODEL);
    gemm_nt_bias<<<gg, tb>>>(K, Wk, bk, gk, M, D_MODEL, D_MODEL);
    gemm_nt_bias<<<gg, tb>>>(V, Wv, bv, gv, M, D_MODEL, D_MODEL);

    flash_attn<<<dim3(S / 64, B * NHEAD), tb, SMEM_FLASH>>>(gq, gk, gv, go, S);

    gemm_nt_bias<<<gg, tb>>>(go, Wo, bo, out, M, D_MODEL, D_MODEL);
}

// round 2
// speedup vs baseline: 2.4930x; 2.4930x over previous
#include <cuda_runtime.h>
#include <math_constants.h>

#define D_MODEL 768
#define NHEAD   12
#define DK      64
#define MAXM    8192   // B*S = 2*4096

// ---- scratch (no cudaMalloc allowed) ----
__device__ float g_q [MAXM * D_MODEL];
__device__ float g_k [MAXM * D_MODEL];
__device__ float g_v [MAXM * D_MODEL];
__device__ float g_ao[MAXM * D_MODEL];

// ---- tf32 helpers ----
__device__ __forceinline__ unsigned f2tf(float x) {
    unsigned u; asm("cvt.rna.tf32.f32 %0, %1;" : "=r"(u) : "f"(x)); return u;
}
__device__ __forceinline__ float f2tff(float x) { return __uint_as_float(f2tf(x)); }

__device__ __forceinline__ void mma_tf32(
    float& c0, float& c1, float& c2, float& c3,
    unsigned a0, unsigned a1, unsigned a2, unsigned a3,
    unsigned b0, unsigned b1)
{
    asm volatile(
        "mma.sync.aligned.m16n8k8.row.col.f32.tf32.tf32.f32 "
        "{%0,%1,%2,%3},{%4,%5,%6,%7},{%8,%9},{%0,%1,%2,%3};"
        : "+f"(c0), "+f"(c1), "+f"(c2), "+f"(c3)
        : "r"(a0), "r"(a1), "r"(a2), "r"(a3), "r"(b0), "r"(b1));
}

// ============================================================================
// NT GEMM via tf32 mma: C[m][n] = bias[n] + sum_k A[m][k] * W[n][k]
// A: MxK row-major, W: NxK row-major (== col-major B), C: MxN row-major.
// Tile 128x64x32, 256 threads (8 warps, 4m x 2n), warp tile 32x32.
// ============================================================================
__global__ __launch_bounds__(256) void gemm_nt_tc(
    const float* __restrict__ A, const float* __restrict__ W,
    const float* __restrict__ bias, float* __restrict__ C,
    int M, int N, int K)
{
    __shared__ float As[128][36];
    __shared__ float Ws[64][36];

    const int tid  = threadIdx.x;
    const int lane = tid & 31, warp = tid >> 5;
    const int g = lane >> 2, t = lane & 3;
    const int wm = (warp >> 1) * 32, wn = (warp & 1) * 32;
    const int bm = blockIdx.y * 128, bn = blockIdx.x * 64;

    const int ar = tid >> 3;            // 0..31
    const int ak = (tid & 7) << 2;      // 0,4,...,28

    float c[2][4][4] = {};

    for (int k0 = 0; k0 < K; k0 += 32) {
#pragma unroll
        for (int i = 0; i < 4; i++) {
            float4 v = *(const float4*)(A + (size_t)(bm + ar + i*32) * K + k0 + ak);
            As[ar + i*32][ak+0] = f2tff(v.x);
            As[ar + i*32][ak+1] = f2tff(v.y);
            As[ar + i*32][ak+2] = f2tff(v.z);
            As[ar + i*32][ak+3] = f2tff(v.w);
        }
#pragma unroll
        for (int i = 0; i < 2; i++) {
            float4 v = *(const float4*)(W + (size_t)(bn + ar + i*32) * K + k0 + ak);
            Ws[ar + i*32][ak+0] = f2tff(v.x);
            Ws[ar + i*32][ak+1] = f2tff(v.y);
            Ws[ar + i*32][ak+2] = f2tff(v.z);
            Ws[ar + i*32][ak+3] = f2tff(v.w);
        }
        __syncthreads();

#pragma unroll
        for (int kk = 0; kk < 4; kk++) {
            const int kb = kk * 8;
            unsigned a[2][4];
#pragma unroll
            for (int mt = 0; mt < 2; mt++) {
                a[mt][0] = __float_as_uint(As[wm + mt*16 + g    ][kb + t    ]);
                a[mt][1] = __float_as_uint(As[wm + mt*16 + g + 8][kb + t    ]);
                a[mt][2] = __float_as_uint(As[wm + mt*16 + g    ][kb + t + 4]);
                a[mt][3] = __float_as_uint(As[wm + mt*16 + g + 8][kb + t + 4]);
            }
#pragma unroll
            for (int nt = 0; nt < 4; nt++) {
                unsigned b0 = __float_as_uint(Ws[wn + nt*8 + g][kb + t    ]);
                unsigned b1 = __float_as_uint(Ws[wn + nt*8 + g][kb + t + 4]);
#pragma unroll
                for (int mt = 0; mt < 2; mt++)
                    mma_tf32(c[mt][nt][0], c[mt][nt][1], c[mt][nt][2], c[mt][nt][3],
                             a[mt][0], a[mt][1], a[mt][2], a[mt][3], b0, b1);
            }
        }
        __syncthreads();
    }

#pragma unroll
    for (int mt = 0; mt < 2; mt++) {
#pragma unroll
        for (int nt = 0; nt < 4; nt++) {
            int row = bm + wm + mt*16 + g;
            int col = bn + wn + nt*8 + 2*t;
            float2 b2 = *(const float2*)(bias + col);
            float2 o0 = make_float2(c[mt][nt][0] + b2.x, c[mt][nt][1] + b2.y);
            *(float2*)(C + (size_t)row * N + col) = o0;
            float2 o1 = make_float2(c[mt][nt][2] + b2.x, c[mt][nt][3] + b2.y);
            *(float2*)(C + (size_t)(row + 8) * N + col) = o1;
        }
    }
}

// ============================================================================
// Flash attention via tf32 mma. CTA = 64 q-rows of one (b,h), 128 threads.
// Warp w owns q rows [16w, 16w+16). KV tile = 64 keys.
// q,k,v,o layout: (B, S, H*DK). scale folded into Q load.
// ============================================================================
#define SMEM_FLASH (4 * 64 * 68 * 4)

__global__ __launch_bounds__(128) void flash_tc(
    const float* __restrict__ Qp, const float* __restrict__ Kp,
    const float* __restrict__ Vp, float* __restrict__ Op, int S)
{
    extern __shared__ float sm[];
    float (*Qs)[68] = (float (*)[68])(sm);             // [q][d]
    float (*Ks)[68] = (float (*)[68])(sm + 1*64*68);   // [key][d]  (= col-major B for QK^T)
    float (*Vt)[68] = (float (*)[68])(sm + 2*64*68);   // [d][key]  (= col-major B for P@V)
    float (*Ps)[68] = (float (*)[68])(sm + 3*64*68);   // [q][key]

    const int tid  = threadIdx.x;
    const int lane = tid & 31, warp = tid >> 5;
    const int g = lane >> 2, t = lane & 3;
    const int wm = warp * 16;
    const int b = blockIdx.y / NHEAD, h = blockIdx.y % NHEAD;
    const int q0 = blockIdx.x * 64;
    const size_t base = ((size_t)b * S) * D_MODEL + (size_t)h * DK;

    // load Q tile (pre-scaled by 1/sqrt(dk)=0.125, tf32-rounded)
#pragma unroll
    for (int p = 0; p < 8; p++) {
        int fl = p * 128 + tid;
        int r = fl >> 4, cc = (fl & 15) << 2;
        float4 v = *(const float4*)(Qp + base + (size_t)(q0 + r) * D_MODEL + cc);
        Qs[r][cc+0] = f2tff(v.x * 0.125f);
        Qs[r][cc+1] = f2tff(v.y * 0.125f);
        Qs[r][cc+2] = f2tff(v.z * 0.125f);
        Qs[r][cc+3] = f2tff(v.w * 0.125f);
    }

    float o[8][4] = {};
    float m0 = -CUDART_INF_F, m1 = -CUDART_INF_F, l0 = 0.f, l1 = 0.f;

    for (int kv0 = 0; kv0 < S; kv0 += 64) {
#pragma unroll
        for (int p = 0; p < 8; p++) {
            int fl = p * 128 + tid;
            int r = fl >> 4, cc = (fl & 15) << 2;
            float4 kv = *(const float4*)(Kp + base + (size_t)(kv0 + r) * D_MODEL + cc);
            Ks[r][cc+0] = f2tff(kv.x);
            Ks[r][cc+1] = f2tff(kv.y);
            Ks[r][cc+2] = f2tff(kv.z);
            Ks[r][cc+3] = f2tff(kv.w);
            float4 vv = *(const float4*)(Vp + base + (size_t)(kv0 + r) * D_MODEL + cc);
            Vt[cc+0][r] = f2tff(vv.x);
            Vt[cc+1][r] = f2tff(vv.y);
            Vt[cc+2][r] = f2tff(vv.z);
            Vt[cc+3][r] = f2tff(vv.w);
        }
        __syncthreads();

        // S = Q @ K^T : warp computes 16x64 (8 n-tiles), k = d = 64 (8 steps)
        float s[8][4] = {};
#pragma unroll
        for (int kk = 0; kk < 8; kk++) {
            const int kb = kk * 8;
            unsigned a0 = __float_as_uint(Qs[wm + g    ][kb + t    ]);
            unsigned a1 = __float_as_uint(Qs[wm + g + 8][kb + t    ]);
            unsigned a2 = __float_as_uint(Qs[wm + g    ][kb + t + 4]);
            unsigned a3 = __float_as_uint(Qs[wm + g + 8][kb + t + 4]);
#pragma unroll
            for (int nt = 0; nt < 8; nt++) {
                unsigned b0 = __float_as_uint(Ks[nt*8 + g][kb + t    ]);
                unsigned b1 = __float_as_uint(Ks[nt*8 + g][kb + t + 4]);
                mma_tf32(s[nt][0], s[nt][1], s[nt][2], s[nt][3], a0, a1, a2, a3, b0, b1);
            }
        }

        // online softmax. row g -> (c0,c1); row g+8 -> (c2,c3); 4-lane quad owns a row.
        float mx0 = -CUDART_INF_F, mx1 = -CUDART_INF_F;
#pragma unroll
        for (int nt = 0; nt < 8; nt++) {
            mx0 = fmaxf(mx0, fmaxf(s[nt][0], s[nt][1]));
            mx1 = fmaxf(mx1, fmaxf(s[nt][2], s[nt][3]));
        }
#pragma unroll
        for (int off = 2; off >= 1; off >>= 1) {
            mx0 = fmaxf(mx0, __shfl_xor_sync(0xffffffffu, mx0, off));
            mx1 = fmaxf(mx1, __shfl_xor_sync(0xffffffffu, mx1, off));
        }
        float mn0 = fmaxf(m0, mx0), mn1 = fmaxf(m1, mx1);
        float al0 = __expf(m0 - mn0), al1 = __expf(m1 - mn1);
        m0 = mn0; m1 = mn1;

        float rs0 = 0.f, rs1 = 0.f;
#pragma unroll
        for (int nt = 0; nt < 8; nt++) {
            float p0 = __expf(s[nt][0] - mn0);
            float p1 = __expf(s[nt][1] - mn0);
            float p2 = __expf(s[nt][2] - mn1);
            float p3 = __expf(s[nt][3] - mn1);
            rs0 += p0 + p1; rs1 += p2 + p3;
            int col = nt*8 + 2*t;
            Ps[wm + g    ][col    ] = f2tff(p0);
            Ps[wm + g    ][col + 1] = f2tff(p1);
            Ps[wm + g + 8][col    ] = f2tff(p2);
            Ps[wm + g + 8][col + 1] = f2tff(p3);
        }
#pragma unroll
        for (int off = 2; off >= 1; off >>= 1) {
            rs0 += __shfl_xor_sync(0xffffffffu, rs0, off);
            rs1 += __shfl_xor_sync(0xffffffffu, rs1, off);
        }
        l0 = l0 * al0 + rs0;
        l1 = l1 * al1 + rs1;
#pragma unroll
        for (int nt = 0; nt < 8; nt++) {
            o[nt][0] *= al0; o[nt][1] *= al0;
            o[nt][2] *= al1; o[nt][3] *= al1;
        }
        __syncwarp();   // Ps is warp-private: make stores visible to quad peers

        // O += P @ V : 16x64 (8 n-tiles over d), k = key = 64 (8 steps)
#pragma unroll
        for (int kk = 0; kk < 8; kk++) {
            const int kb = kk * 8;
            unsigned a0 = __float_as_uint(Ps[wm + g    ][kb + t    ]);
            unsigned a1 = __float_as_uint(Ps[wm + g + 8][kb + t    ]);
            unsigned a2 = __float_as_uint(Ps[wm + g    ][kb + t + 4]);
            unsigned a3 = __float_as_uint(Ps[wm + g + 8][kb + t + 4]);
#pragma unroll
            for (int nt = 0; nt < 8; nt++) {
                unsigned b0 = __float_as_uint(Vt[nt*8 + g][kb + t    ]);
                unsigned b1 = __float_as_uint(Vt[nt*8 + g][kb + t + 4]);
                mma_tf32(o[nt][0], o[nt][1], o[nt][2], o[nt][3], a0, a1, a2, a3, b0, b1);
            }
        }
        __syncthreads();   // Ks/Vt (and Ps vs next-iter stores) reuse
    }

    // epilogue: normalize, write (B,S,H*DK) layout (head-merge free)
    float inv0 = 1.f / l0, inv1 = 1.f / l1;
#pragma unroll
    for (int nt = 0; nt < 8; nt++) {
        int col = nt*8 + 2*t;
        float2 o0 = make_float2(o[nt][0] * inv0, o[nt][1] * inv0);
        *(float2*)(Op + base + (size_t)(q0 + wm + g) * D_MODEL + col) = o0;
        float2 o1 = make_float2(o[nt][2] * inv1, o[nt][3] * inv1);
        *(float2*)(Op + base + (size_t)(q0 + wm + g + 8) * D_MODEL + col) = o1;
    }
}

// ============================================================================
extern "C" void kernel_launch(void* const* d_in, const int* in_sizes, int n_in,
                              void* d_out, int out_size)
{
    const float* Q  = (const float*)d_in[0];
    const float* K  = (const float*)d_in[1];
    const float* V  = (const float*)d_in[2];
    const float* Wq = (const float*)d_in[3];
    const float* bq = (const float*)d_in[4];
    const float* Wk = (const float*)d_in[5];
    const float* bk = (const float*)d_in[6];
    const float* Wv = (const float*)d_in[7];
    const float* bv = (const float*)d_in[8];
    const float* Wo = (const float*)d_in[9];
    const float* bo = (const float*)d_in[10];
    float* out = (float*)d_out;

    const int M = in_sizes[0] / D_MODEL;   // B*S
    const int S = 4096;
    const int B = M / S;

    float *gq, *gk, *gv, *go;
    cudaGetSymbolAddress((void**)&gq, g_q);
    cudaGetSymbolAddress((void**)&gk, g_k);
    cudaGetSymbolAddress((void**)&gv, g_v);
    cudaGetSymbolAddress((void**)&go, g_ao);

    cudaFuncSetAttribute(flash_tc, cudaFuncAttributeMaxDynamicSharedMemorySize, SMEM_FLASH);

    dim3 tb(256);
    dim3 gg(D_MODEL / 64, M / 128);
    gemm_nt_tc<<<gg, tb>>>(Q, Wq, bq, gq, M, D_MODEL, D_MODEL);
    gemm_nt_tc<<<gg, tb>>>(K, Wk, bk, gk, M, D_MODEL, D_MODEL);
    gemm_nt_tc<<<gg, tb>>>(V, Wv, bv, gv, M, D_MODEL, D_MODEL);

    flash_tc<<<dim3(S / 64, B * NHEAD), dim3(128), SMEM_FLASH>>>(gq, gk, gv, go, S);

    gemm_nt_tc<<<gg, tb>>>(go, Wo, bo, out, M, D_MODEL, D_MODEL);
}

// round 3
// speedup vs baseline: 3.2635x; 1.3091x over previous
#include <cuda_runtime.h>
#include <math_constants.h>

#define D_MODEL 768
#define NHEAD   12
#define DK      64
#define MAXM    8192   // B*S = 2*4096

// ---- scratch (no cudaMalloc allowed) ----
__device__ float g_q [MAXM * D_MODEL];
__device__ float g_k [MAXM * D_MODEL];
__device__ float g_v [MAXM * D_MODEL];
__device__ float g_ao[MAXM * D_MODEL];

// ---- tf32 helpers ----
__device__ __forceinline__ float f2tff(float x) {
    unsigned u; asm("cvt.rna.tf32.f32 %0, %1;" : "=r"(u) : "f"(x));
    return __uint_as_float(u);
}

__device__ __forceinline__ void mma_tf32(
    float& c0, float& c1, float& c2, float& c3,
    float a0, float a1, float a2, float a3,
    float b0, float b1)
{
    asm volatile(
        "mma.sync.aligned.m16n8k8.row.col.f32.tf32.tf32.f32 "
        "{%0,%1,%2,%3},{%4,%5,%6,%7},{%8,%9},{%0,%1,%2,%3};"
        : "+f"(c0), "+f"(c1), "+f"(c2), "+f"(c3)
        : "r"(__float_as_uint(a0)), "r"(__float_as_uint(a1)),
          "r"(__float_as_uint(a2)), "r"(__float_as_uint(a3)),
          "r"(__float_as_uint(b0)), "r"(__float_as_uint(b1)));
}

// Fragment-packed smem layouts (per 16x8 / 8x8 mma blocks):
//  A-pack: addr = blk*132 + lane*4 + reg   (reg = hi + 2*h) -> LDS.128/thread
//  B-pack: addr = blk*BS  + lane*2 + h     -> LDS.64/thread
// where element (row r, col c) of the operand tile maps:
//  A: g=r%8, hi=(r%16)/8, t=c%4, h=(c%8)/4, lane=4g+t
//  B: g=n%8 (n-dim),      t=k%4, h=(k%8)/4, lane=4g+t

// ============================================================================
// NT GEMM via tf32 mma: C[m][n] = bias[n] + sum_k A[m][k] * W[n][k]
// Tile 128x64x32, 256 threads (8 warps, 4m x 2n), warp tile 32x32.
// ============================================================================
__global__ __launch_bounds__(256) void gemm_nt_tc(
    const float* __restrict__ A, const float* __restrict__ W,
    const float* __restrict__ bias, float* __restrict__ C,
    int M, int N, int K)
{
    __shared__ float Af[32 * 132];   // blk = rt*4 + kk  (rt 0..7, kk 0..3)
    __shared__ float Wf[32 * 66];    // blk = nt*4 + kk  (nt 0..7, kk 0..3)

    const int tid  = threadIdx.x;
    const int lane = tid & 31, warp = tid >> 5;
    const int g = lane >> 2, t = lane & 3;
    const int rm = warp >> 1;            // warp m-group (0..3) -> rows rm*32
    const int wn = warp & 1;             // warp n-group (0..1) -> nt base wn*4
    const int bm = blockIdx.y * 128, bn = blockIdx.x * 64;

    float c[2][4][4] = {};

    for (int k0 = 0; k0 < K; k0 += 32) {
        // stage A (128x32) fragment-packed
#pragma unroll
        for (int p = 0; p < 4; p++) {
            int fl = p * 256 + tid;
            int r = fl >> 3, cc = (fl & 7) << 2;
            float4 v = *(const float4*)(A + (size_t)(bm + r) * K + k0 + cc);
            int rt = r >> 4, gg = r & 7, hi = (r >> 3) & 1;
            int kk = cc >> 3, hh = (cc >> 2) & 1;
            int dst = (rt*4 + kk)*132 + 16*gg + hi + 2*hh;
            Af[dst     ] = f2tff(v.x);
            Af[dst +  4] = f2tff(v.y);
            Af[dst +  8] = f2tff(v.z);
            Af[dst + 12] = f2tff(v.w);
        }
        // stage W (64x32) fragment-packed
#pragma unroll
        for (int p = 0; p < 2; p++) {
            int fl = p * 256 + tid;
            int r = fl >> 3, cc = (fl & 7) << 2;
            float4 v = *(const float4*)(W + (size_t)(bn + r) * K + k0 + cc);
            int nt = r >> 3, gg = r & 7;
            int kk = cc >> 3, hh = (cc >> 2) & 1;
            int dst = (nt*4 + kk)*66 + 8*gg + hh;
            Wf[dst    ] = f2tff(v.x);
            Wf[dst + 2] = f2tff(v.y);
            Wf[dst + 4] = f2tff(v.z);
            Wf[dst + 6] = f2tff(v.w);
        }
        __syncthreads();

#pragma unroll
        for (int kk = 0; kk < 4; kk++) {
            float4 a[2];
#pragma unroll
            for (int mt = 0; mt < 2; mt++)
                a[mt] = *(const float4*)&Af[((rm*2 + mt)*4 + kk)*132 + lane*4];
#pragma unroll
            for (int nt = 0; nt < 4; nt++) {
                float2 b2 = *(const float2*)&Wf[((wn*4 + nt)*4 + kk)*66 + lane*2];
#pragma unroll
                for (int mt = 0; mt < 2; mt++)
                    mma_tf32(c[mt][nt][0], c[mt][nt][1], c[mt][nt][2], c[mt][nt][3],
                             a[mt].x, a[mt].y, a[mt].z, a[mt].w, b2.x, b2.y);
            }
        }
        __syncthreads();
    }

#pragma unroll
    for (int mt = 0; mt < 2; mt++) {
#pragma unroll
        for (int nt = 0; nt < 4; nt++) {
            int row = bm + rm*32 + mt*16 + g;
            int col = bn + wn*32 + nt*8 + 2*t;
            float2 b2 = *(const float2*)(bias + col);
            *(float2*)(C + (size_t)row * N + col) =
                make_float2(c[mt][nt][0] + b2.x, c[mt][nt][1] + b2.y);
            *(float2*)(C + (size_t)(row + 8) * N + col) =
                make_float2(c[mt][nt][2] + b2.x, c[mt][nt][3] + b2.y);
        }
    }
}

// ============================================================================
// Flash attention, tf32 mma, fragment-packed smem.
// CTA = 128 q-rows of one (b,h), 128 threads, warp owns 32 q-rows.
// KV tile = 64 keys. q,k,v,o layout: (B, S, H*DK).
// ============================================================================
// smem (floats): Qf 8448 | Kf 4224 | Vf 4352 | Ps 128x68=8704  -> 25728 floats
#define OFF_KF 8448
#define OFF_VF 12672
#define OFF_PS 17024
#define SMEM_FLASH (25728 * 4)

__global__ __launch_bounds__(128) void flash_tc(
    const float* __restrict__ Qp, const float* __restrict__ Kp,
    const float* __restrict__ Vp, float* __restrict__ Op, int S)
{
    extern __shared__ float sm[];
    float* Qf = sm;                 // blk=(rt*8+kk)*132, rt 0..7, kk 0..7
    float* Kf = sm + OFF_KF;        // blk=(nt*8+kk)*66   (n=key, k=d)
    float* Vf = sm + OFF_VF;        // blk=(kk*8+nt)*68   (n=d, k=key)
    float (*Ps)[68] = (float (*)[68])(sm + OFF_PS);

    const int tid  = threadIdx.x;
    const int lane = tid & 31, warp = tid >> 5;
    const int g = lane >> 2, t = lane & 3;
    const int b = blockIdx.y / NHEAD, h = blockIdx.y % NHEAD;
    const int q0 = blockIdx.x * 128;
    const size_t base = ((size_t)b * S) * D_MODEL + (size_t)h * DK;

    // stage Q (128x64), fragment-packed, pre-scaled by 1/8
#pragma unroll
    for (int p = 0; p < 16; p++) {
        int fl = p * 128 + tid;
        int r = fl >> 4, cc = (fl & 15) << 2;
        float4 v = *(const float4*)(Qp + base + (size_t)(q0 + r) * D_MODEL + cc);
        int rt = r >> 4, gg = r & 7, hi = (r >> 3) & 1;
        int kk = cc >> 3, hh = (cc >> 2) & 1;
        int dst = (rt*8 + kk)*132 + 16*gg + hi + 2*hh;
        Qf[dst     ] = f2tff(v.x * 0.125f);
        Qf[dst +  4] = f2tff(v.y * 0.125f);
        Qf[dst +  8] = f2tff(v.z * 0.125f);
        Qf[dst + 12] = f2tff(v.w * 0.125f);
    }

    float o[2][8][4] = {};
    float m_[2][2], l_[2][2];
#pragma unroll
    for (int mt = 0; mt < 2; mt++) {
        m_[mt][0] = m_[mt][1] = -CUDART_INF_F;
        l_[mt][0] = l_[mt][1] = 0.f;
    }

    for (int kv0 = 0; kv0 < S; kv0 += 64) {
        // stage K (64 keys x 64 d): B-pack with n=key, k=d
#pragma unroll
        for (int p = 0; p < 8; p++) {
            int fl = p * 128 + tid;
            int r = fl >> 4, cc = (fl & 15) << 2;
            float4 v = *(const float4*)(Kp + base + (size_t)(kv0 + r) * D_MODEL + cc);
            int nt = r >> 3, gg = r & 7;
            int kk = cc >> 3, hh = (cc >> 2) & 1;
            int dst = (nt*8 + kk)*66 + 8*gg + hh;
            Kf[dst    ] = f2tff(v.x);
            Kf[dst + 2] = f2tff(v.y);
            Kf[dst + 4] = f2tff(v.z);
            Kf[dst + 6] = f2tff(v.w);
        }
        // stage V (64 keys x 64 d): B-pack with n=d, k=key
#pragma unroll
        for (int p = 0; p < 8; p++) {
            int fl = p * 128 + tid;
            int r = fl >> 4, cc = (fl & 15) << 2;   // r = key, cc = d col
            float4 v = *(const float4*)(Vp + base + (size_t)(kv0 + r) * D_MODEL + cc);
            int kk = r >> 3, tt = r & 3, hh = (r >> 2) & 1;
            int nt = cc >> 3, g0 = cc & 7;
            int dst = (kk*8 + nt)*68 + 8*g0 + 2*tt + hh;
            Vf[dst     ] = f2tff(v.x);
            Vf[dst +  8] = f2tff(v.y);
            Vf[dst + 16] = f2tff(v.z);
            Vf[dst + 24] = f2tff(v.w);
        }
        __syncthreads();

        // S = Q @ K^T : per warp 32x64 (2 m-tiles x 8 n-tiles), k=d=64
        float s[2][8][4] = {};
#pragma unroll
        for (int kk = 0; kk < 8; kk++) {
            float4 a[2];
#pragma unroll
            for (int mt = 0; mt < 2; mt++)
                a[mt] = *(const float4*)&Qf[((2*warp + mt)*8 + kk)*132 + lane*4];
#pragma unroll
            for (int nt = 0; nt < 8; nt++) {
                float2 b2 = *(const float2*)&Kf[(nt*8 + kk)*66 + lane*2];
#pragma unroll
                for (int mt = 0; mt < 2; mt++)
                    mma_tf32(s[mt][nt][0], s[mt][nt][1], s[mt][nt][2], s[mt][nt][3],
                             a[mt].x, a[mt].y, a[mt].z, a[mt].w, b2.x, b2.y);
            }
        }

        // online softmax (quad of 4 lanes owns a row) + stage P
#pragma unroll
        for (int mt = 0; mt < 2; mt++) {
            int rbase = 32*warp + 16*mt;
            float mx0 = -CUDART_INF_F, mx1 = -CUDART_INF_F;
#pragma unroll
            for (int nt = 0; nt < 8; nt++) {
                mx0 = fmaxf(mx0, fmaxf(s[mt][nt][0], s[mt][nt][1]));
                mx1 = fmaxf(mx1, fmaxf(s[mt][nt][2], s[mt][nt][3]));
            }
#pragma unroll
            for (int off = 2; off >= 1; off >>= 1) {
                mx0 = fmaxf(mx0, __shfl_xor_sync(0xffffffffu, mx0, off));
                mx1 = fmaxf(mx1, __shfl_xor_sync(0xffffffffu, mx1, off));
            }
            float mn0 = fmaxf(m_[mt][0], mx0), mn1 = fmaxf(m_[mt][1], mx1);
            float al0 = __expf(m_[mt][0] - mn0), al1 = __expf(m_[mt][1] - mn1);
            m_[mt][0] = mn0; m_[mt][1] = mn1;

            float rs0 = 0.f, rs1 = 0.f;
#pragma unroll
            for (int nt = 0; nt < 8; nt++) {
                float p0 = __expf(s[mt][nt][0] - mn0);
                float p1 = __expf(s[mt][nt][1] - mn0);
                float p2 = __expf(s[mt][nt][2] - mn1);
                float p3 = __expf(s[mt][nt][3] - mn1);
                rs0 += p0 + p1; rs1 += p2 + p3;
                int col = nt*8 + 2*t;
                *(float2*)&Ps[rbase + g    ][col] = make_float2(f2tff(p0), f2tff(p1));
                *(float2*)&Ps[rbase + g + 8][col] = make_float2(f2tff(p2), f2tff(p3));
            }
#pragma unroll
            for (int off = 2; off >= 1; off >>= 1) {
                rs0 += __shfl_xor_sync(0xffffffffu, rs0, off);
                rs1 += __shfl_xor_sync(0xffffffffu, rs1, off);
            }
            l_[mt][0] = l_[mt][0] * al0 + rs0;
            l_[mt][1] = l_[mt][1] * al1 + rs1;
#pragma unroll
            for (int nt = 0; nt < 8; nt++) {
                o[mt][nt][0] *= al0; o[mt][nt][1] *= al0;
                o[mt][nt][2] *= al1; o[mt][nt][3] *= al1;
            }
        }
        __syncwarp();   // Ps rows are warp-private

        // O += P @ V : k=key=64
#pragma unroll
        for (int kk = 0; kk < 8; kk++) {
            const int kb = kk * 8;
            float a[2][4];
#pragma unroll
            for (int mt = 0; mt < 2; mt++) {
                int rbase = 32*warp + 16*mt;
                a[mt][0] = Ps[rbase + g    ][kb + t    ];
                a[mt][1] = Ps[rbase + g + 8][kb + t    ];
                a[mt][2] = Ps[rbase + g    ][kb + t + 4];
                a[mt][3] = Ps[rbase + g + 8][kb + t + 4];
            }
#pragma unroll
            for (int nt = 0; nt < 8; nt++) {
                float2 b2 = *(const float2*)&Vf[(kk*8 + nt)*68 + lane*2];
#pragma unroll
                for (int mt = 0; mt < 2; mt++)
                    mma_tf32(o[mt][nt][0], o[mt][nt][1], o[mt][nt][2], o[mt][nt][3],
                             a[mt][0], a[mt][1], a[mt][2], a[mt][3], b2.x, b2.y);
            }
        }
        __syncthreads();   // Kf/Vf reuse next iter
    }

    // epilogue: normalize, write (B,S,H*DK) layout
#pragma unroll
    for (int mt = 0; mt < 2; mt++) {
        float inv0 = 1.f / l_[mt][0], inv1 = 1.f / l_[mt][1];
        int row = q0 + 32*warp + 16*mt + g;
#pragma unroll
        for (int nt = 0; nt < 8; nt++) {
            int col = nt*8 + 2*t;
            *(float2*)(Op + base + (size_t)row * D_MODEL + col) =
                make_float2(o[mt][nt][0]*inv0, o[mt][nt][1]*inv0);
            *(float2*)(Op + base + (size_t)(row + 8) * D_MODEL + col) =
                make_float2(o[mt][nt][2]*inv1, o[mt][nt][3]*inv1);
        }
    }
}

// ============================================================================
extern "C" void kernel_launch(void* const* d_in, const int* in_sizes, int n_in,
                              void* d_out, int out_size)
{
    const float* Q  = (const float*)d_in[0];
    const float* K  = (const float*)d_in[1];
    const float* V  = (const float*)d_in[2];
    const float* Wq = (const float*)d_in[3];
    const float* bq = (const float*)d_in[4];
    const float* Wk = (const float*)d_in[5];
    const float* bk = (const float*)d_in[6];
    const float* Wv = (const float*)d_in[7];
    const float* bv = (const float*)d_in[8];
    const float* Wo = (const float*)d_in[9];
    const float* bo = (const float*)d_in[10];
    float* out = (float*)d_out;

    const int M = in_sizes[0] / D_MODEL;   // B*S
    const int S = 4096;
    const int B = M / S;

    float *gq, *gk, *gv, *go;
    cudaGetSymbolAddress((void**)&gq, g_q);
    cudaGetSymbolAddress((void**)&gk, g_k);
    cudaGetSymbolAddress((void**)&gv, g_v);
    cudaGetSymbolAddress((void**)&go, g_ao);

    cudaFuncSetAttribute(flash_tc, cudaFuncAttributeMaxDynamicSharedMemorySize, SMEM_FLASH);

    dim3 tb(256);
    dim3 gg(D_MODEL / 64, M / 128);
    gemm_nt_tc<<<gg, tb>>>(Q, Wq, bq, gq, M, D_MODEL, D_MODEL);
    gemm_nt_tc<<<gg, tb>>>(K, Wk, bk, gk, M, D_MODEL, D_MODEL);
    gemm_nt_tc<<<gg, tb>>>(V, Wv, bv, gv, M, D_MODEL, D_MODEL);

    flash_tc<<<dim3(S / 128, B * NHEAD), dim3(128), SMEM_FLASH>>>(gq, gk, gv, go, S);

    gemm_nt_tc<<<gg, tb>>>(go, Wo, bo, out, M, D_MODEL, D_MODEL);
}